// round 1
// baseline (speedup 1.0000x reference)
#include <cuda_runtime.h>
#include <math_constants.h>

#define D_MODEL   1024
#define NUM_HEADS 16
#define D_HEAD    64
#define PATCH     128
#define BATCH     4
#define SEQ       8192
#define M_TOTAL   (BATCH * SEQ)          // 32768 rows
#define NBLK      (M_TOTAL / PATCH)      // 256 patch blocks

// Scratch (static device globals — no runtime allocation)
__device__ float g_Q[(size_t)M_TOTAL * D_MODEL];
__device__ float g_K[(size_t)M_TOTAL * D_MODEL];
__device__ float g_V[(size_t)M_TOTAL * D_MODEL];
__device__ float g_A[(size_t)M_TOTAL * D_MODEL];

// ---------------------------------------------------------------------------
// SGEMM: C[M,N] = A[M,K] @ B[K,N] + bias[N]
// BM=128, BN=128, BK=16, 256 threads, 8x8 per thread.
// M=32768, N=K=1024 (all divide tile sizes evenly; no bounds checks).
// ---------------------------------------------------------------------------
__global__ __launch_bounds__(256, 2)
void sgemm_bias_kernel(const float* __restrict__ A,
                       const float* __restrict__ B,
                       const float* __restrict__ bias,
                       float* __restrict__ C,
                       int M, int N, int K)
{
    __shared__ float As[16][128];
    __shared__ float Bs[16][128];

    const int tid = threadIdx.x;
    const int bm  = blockIdx.y;
    const int bn  = blockIdx.x;
    const int tm  = tid >> 4;   // 0..15
    const int tn  = tid & 15;   // 0..15

    const float* Ab = A + (size_t)bm * 128 * K;
    const float* Bb = B + (size_t)bn * 128;

    float acc[8][8];
    #pragma unroll
    for (int i = 0; i < 8; i++)
        #pragma unroll
        for (int j = 0; j < 8; j++) acc[i][j] = 0.0f;

    for (int kk = 0; kk < K; kk += 16) {
        // Load A tile 128x16 (store transposed: As[k][m])
        #pragma unroll
        for (int i = 0; i < 2; i++) {
            int f   = tid * 2 + i;        // 0..511 float4s
            int row = f >> 2;             // 0..127
            int c4  = f & 3;              // 0..3
            float4 a = *reinterpret_cast<const float4*>(Ab + (size_t)row * K + kk + c4 * 4);
            As[c4 * 4 + 0][row] = a.x;
            As[c4 * 4 + 1][row] = a.y;
            As[c4 * 4 + 2][row] = a.z;
            As[c4 * 4 + 3][row] = a.w;
        }
        // Load B tile 16x128
        #pragma unroll
        for (int i = 0; i < 2; i++) {
            int f   = tid * 2 + i;        // 0..511
            int row = f >> 5;             // 0..15
            int c4  = f & 31;             // 0..31
            float4 b = *reinterpret_cast<const float4*>(Bb + (size_t)(kk + row) * N + c4 * 4);
            *reinterpret_cast<float4*>(&Bs[row][c4 * 4]) = b;
        }
        __syncthreads();

        #pragma unroll
        for (int k = 0; k < 16; k++) {
            float af[8], bf[8];
            *reinterpret_cast<float4*>(&af[0]) = *reinterpret_cast<float4*>(&As[k][tm * 8 + 0]);
            *reinterpret_cast<float4*>(&af[4]) = *reinterpret_cast<float4*>(&As[k][tm * 8 + 4]);
            *reinterpret_cast<float4*>(&bf[0]) = *reinterpret_cast<float4*>(&Bs[k][tn * 8 + 0]);
            *reinterpret_cast<float4*>(&bf[4]) = *reinterpret_cast<float4*>(&Bs[k][tn * 8 + 4]);
            #pragma unroll
            for (int i = 0; i < 8; i++)
                #pragma unroll
                for (int j = 0; j < 8; j++)
                    acc[i][j] += af[i] * bf[j];
        }
        __syncthreads();
    }

    // Epilogue: + bias, vectorized stores
    #pragma unroll
    for (int i = 0; i < 8; i++) {
        size_t row = (size_t)bm * 128 + tm * 8 + i;
        float* cp = C + row * N + bn * 128 + tn * 8;
        const float* bp = bias + bn * 128 + tn * 8;
        #pragma unroll
        for (int j = 0; j < 8; j += 4) {
            float4 o;
            o.x = acc[i][j + 0] + bp[j + 0];
            o.y = acc[i][j + 1] + bp[j + 1];
            o.z = acc[i][j + 2] + bp[j + 2];
            o.w = acc[i][j + 3] + bp[j + 3];
            *reinterpret_cast<float4*>(cp + j) = o;
        }
    }
}

// ---------------------------------------------------------------------------
// Fused patch attention: one CTA per (patch-block, head).
// grid = (NUM_HEADS, NBLK), 256 threads.
// smem: Ks[128][64], Vs[128][64], S[128][129]  -> 131584 bytes (dynamic)
// Thread t handles row r = t/2, half = t&1.
// ---------------------------------------------------------------------------
__global__ __launch_bounds__(256, 1)
void attn_kernel()
{
    extern __shared__ float sm[];
    float* Ks = sm;                  // 128*64
    float* Vs = Ks + 128 * 64;       // 128*64
    float* S  = Vs + 128 * 64;       // 128*129 (row pad -> conflict-free)

    const int h   = blockIdx.x;
    const int pb  = blockIdx.y;
    const int tid = threadIdx.x;
    const size_t base = (size_t)pb * 128 * D_MODEL + (size_t)h * D_HEAD;

    // Stage K and V tiles (coalesced float4 loads)
    for (int i = tid; i < 128 * 16; i += 256) {     // float4 index
        int row = i >> 4;
        int c   = i & 15;
        size_t g = base + (size_t)row * D_MODEL + c * 4;
        *reinterpret_cast<float4*>(&Ks[row * 64 + c * 4]) =
            *reinterpret_cast<const float4*>(&g_K[g]);
        *reinterpret_cast<float4*>(&Vs[row * 64 + c * 4]) =
            *reinterpret_cast<const float4*>(&g_V[g]);
    }
    __syncthreads();

    const int r    = tid >> 1;
    const int half = tid & 1;

    // Load this thread's query row (pre-scaled by 1/sqrt(Dh) = 0.125)
    float q[64];
    {
        const float* qp = &g_Q[base + (size_t)r * D_MODEL];
        #pragma unroll
        for (int c = 0; c < 16; c++) {
            float4 v = *reinterpret_cast<const float4*>(qp + c * 4);
            q[c * 4 + 0] = v.x * 0.125f;
            q[c * 4 + 1] = v.y * 0.125f;
            q[c * 4 + 2] = v.z * 0.125f;
            q[c * 4 + 3] = v.w * 0.125f;
        }
    }

    // Phase 1: scores for keys [half*64, half*64+64)
    #pragma unroll 1
    for (int j0 = 0; j0 < 64; j0++) {
        int j = half * 64 + j0;
        const float* kp = &Ks[j * 64];
        float s0 = 0.f, s1 = 0.f, s2 = 0.f, s3 = 0.f;
        #pragma unroll
        for (int c = 0; c < 16; c++) {
            float4 kv = *reinterpret_cast<const float4*>(kp + c * 4);
            s0 += q[c * 4 + 0] * kv.x;
            s1 += q[c * 4 + 1] * kv.y;
            s2 += q[c * 4 + 2] * kv.z;
            s3 += q[c * 4 + 3] * kv.w;
        }
        S[r * 129 + j] = (s0 + s1) + (s2 + s3);
    }
    __syncthreads();

    // Phase 2: softmax over row r (pair of threads cooperates via shfl)
    float mx = -CUDART_INF_F;
    #pragma unroll 4
    for (int j0 = 0; j0 < 64; j0++)
        mx = fmaxf(mx, S[r * 129 + half * 64 + j0]);
    mx = fmaxf(mx, __shfl_xor_sync(0xffffffffu, mx, 1));

    float l = 0.f;
    #pragma unroll 4
    for (int j0 = 0; j0 < 64; j0++) {
        float e = __expf(S[r * 129 + half * 64 + j0] - mx);
        S[r * 129 + half * 64 + j0] = e;
        l += e;
    }
    l += __shfl_xor_sync(0xffffffffu, l, 1);
    float inv = 1.0f / l;
    __syncthreads();

    // Phase 3: out[r][d] for d in [half*32, half*32+32)
    float acc[32];
    #pragma unroll
    for (int c = 0; c < 32; c++) acc[c] = 0.f;

    #pragma unroll 1
    for (int j = 0; j < 128; j++) {
        float w = S[r * 129 + j];
        const float* vp = &Vs[j * 64 + half * 32];
        #pragma unroll
        for (int c = 0; c < 8; c++) {
            float4 vv = *reinterpret_cast<const float4*>(vp + c * 4);
            acc[c * 4 + 0] += w * vv.x;
            acc[c * 4 + 1] += w * vv.y;
            acc[c * 4 + 2] += w * vv.z;
            acc[c * 4 + 3] += w * vv.w;
        }
    }

    float* op = &g_A[base + (size_t)r * D_MODEL + half * 32];
    #pragma unroll
    for (int c = 0; c < 8; c++) {
        float4 o;
        o.x = acc[c * 4 + 0] * inv;
        o.y = acc[c * 4 + 1] * inv;
        o.z = acc[c * 4 + 2] * inv;
        o.w = acc[c * 4 + 3] * inv;
        *reinterpret_cast<float4*>(op + c * 4) = o;
    }
}

// ---------------------------------------------------------------------------
extern "C" void kernel_launch(void* const* d_in, const int* in_sizes, int n_in,
                              void* d_out, int out_size)
{
    const float* x  = (const float*)d_in[0];
    // d_in[1] = coords (unused by reference)
    const float* Wq = (const float*)d_in[2];
    const float* bq = (const float*)d_in[3];
    const float* Wk = (const float*)d_in[4];
    const float* bk = (const float*)d_in[5];
    const float* Wv = (const float*)d_in[6];
    const float* bv = (const float*)d_in[7];
    const float* Wo = (const float*)d_in[8];
    const float* bo = (const float*)d_in[9];
    float* out = (float*)d_out;

    float *pQ, *pK, *pV, *pA;
    cudaGetSymbolAddress((void**)&pQ, g_Q);
    cudaGetSymbolAddress((void**)&pK, g_K);
    cudaGetSymbolAddress((void**)&pV, g_V);
    cudaGetSymbolAddress((void**)&pA, g_A);

    const int M = M_TOTAL, N = D_MODEL, K = D_MODEL;
    dim3 ggrid(N / 128, M / 128);   // (8, 256)

    sgemm_bias_kernel<<<ggrid, 256>>>(x, Wq, bq, pQ, M, N, K);
    sgemm_bias_kernel<<<ggrid, 256>>>(x, Wk, bk, pK, M, N, K);
    sgemm_bias_kernel<<<ggrid, 256>>>(x, Wv, bv, pV, M, N, K);

    static const size_t attn_smem = (128 * 64 * 2 + 128 * 129) * sizeof(float); // 131584
    cudaFuncSetAttribute(attn_kernel, cudaFuncAttributeMaxDynamicSharedMemorySize,
                         (int)attn_smem);
    dim3 agrid(NUM_HEADS, NBLK);    // (16, 256)
    attn_kernel<<<agrid, 256, attn_smem>>>();

    sgemm_bias_kernel<<<ggrid, 256>>>(pA, Wo, bo, out, M, N, K);
}

// round 3
// speedup vs baseline: 1.8546x; 1.8546x over previous
#include <cuda_runtime.h>
#include <cuda_bf16.h>
#include <math_constants.h>
#include <cstdint>

#define D_MODEL   1024
#define NUM_HEADS 16
#define D_HEAD    64
#define PATCH     128
#define BATCH     4
#define SEQ       8192
#define M_TOTAL   (BATCH * SEQ)          // 32768 rows
#define NBLK      (M_TOTAL / PATCH)      // 256 patch blocks

// ---------------------------------------------------------------------------
// Scratch (static device globals — no runtime allocation)
// ---------------------------------------------------------------------------
__device__ __nv_bfloat16 g_xh[(size_t)M_TOTAL * D_MODEL];
__device__ __nv_bfloat16 g_xl[(size_t)M_TOTAL * D_MODEL];
__device__ float         g_Q [(size_t)M_TOTAL * D_MODEL];
__device__ float         g_K [(size_t)M_TOTAL * D_MODEL];
__device__ float         g_V [(size_t)M_TOTAL * D_MODEL];
__device__ __nv_bfloat16 g_Ah[(size_t)M_TOTAL * D_MODEL];
__device__ __nv_bfloat16 g_Al[(size_t)M_TOTAL * D_MODEL];
// transposed+split weights (W^T: row n, col k) — bf16 hi/lo
__device__ __nv_bfloat16 g_wqh[D_MODEL * D_MODEL];
__device__ __nv_bfloat16 g_wql[D_MODEL * D_MODEL];
__device__ __nv_bfloat16 g_wkh[D_MODEL * D_MODEL];
__device__ __nv_bfloat16 g_wkl[D_MODEL * D_MODEL];
__device__ __nv_bfloat16 g_wvh[D_MODEL * D_MODEL];
__device__ __nv_bfloat16 g_wvl[D_MODEL * D_MODEL];
__device__ __nv_bfloat16 g_woh[D_MODEL * D_MODEL];
__device__ __nv_bfloat16 g_wol[D_MODEL * D_MODEL];

// ---------------------------------------------------------------------------
// PTX helpers (base ISA only — no sm_103a-specific features)
// ---------------------------------------------------------------------------
__device__ __forceinline__ uint32_t smem_u32(const void* p) {
    uint32_t a;
    asm("{ .reg .u64 t; cvta.to.shared.u64 t, %1; cvt.u32.u64 %0, t; }" : "=r"(a) : "l"(p));
    return a;
}
__device__ __forceinline__ void cp16(uint32_t dst, const void* src) {
    asm volatile("cp.async.cg.shared.global [%0], [%1], 16;" :: "r"(dst), "l"(src));
}
#define CP_COMMIT() asm volatile("cp.async.commit_group;" ::: "memory")
#define CP_WAIT2()  asm volatile("cp.async.wait_group 2;" ::: "memory")

#define LDSM4(r0, r1, r2, r3, addr) \
    asm volatile("ldmatrix.sync.aligned.m8n8.x4.shared.b16 {%0,%1,%2,%3}, [%4];" \
        : "=r"(r0), "=r"(r1), "=r"(r2), "=r"(r3) : "r"(addr))

#define MMA16816(c, a, b0, b1) \
    asm volatile("mma.sync.aligned.m16n8k16.row.col.f32.bf16.bf16.f32 " \
        "{%0,%1,%2,%3}, {%4,%5,%6,%7}, {%8,%9}, {%0,%1,%2,%3};" \
        : "+f"((c)[0]), "+f"((c)[1]), "+f"((c)[2]), "+f"((c)[3]) \
        : "r"((a)[0]), "r"((a)[1]), "r"((a)[2]), "r"((a)[3]), "r"(b0), "r"(b1))

// ---------------------------------------------------------------------------
// Split fp32 -> bf16 hi/lo (vectorized, grid-stride)
// ---------------------------------------------------------------------------
__global__ void fsplit_kernel(const float4* __restrict__ in,
                              __nv_bfloat162* __restrict__ hi,
                              __nv_bfloat162* __restrict__ lo, int n4)
{
    for (int i = blockIdx.x * blockDim.x + threadIdx.x; i < n4; i += gridDim.x * blockDim.x) {
        float4 v = in[i];
        __nv_bfloat16 hx = __float2bfloat16_rn(v.x);
        __nv_bfloat16 hy = __float2bfloat16_rn(v.y);
        __nv_bfloat16 hz = __float2bfloat16_rn(v.z);
        __nv_bfloat16 hw = __float2bfloat16_rn(v.w);
        __nv_bfloat162 h0; h0.x = hx; h0.y = hy;
        __nv_bfloat162 h1; h1.x = hz; h1.y = hw;
        __nv_bfloat162 l0, l1;
        l0.x = __float2bfloat16_rn(v.x - __bfloat162float(hx));
        l0.y = __float2bfloat16_rn(v.y - __bfloat162float(hy));
        l1.x = __float2bfloat16_rn(v.z - __bfloat162float(hz));
        l1.y = __float2bfloat16_rn(v.w - __bfloat162float(hw));
        hi[i * 2 + 0] = h0; hi[i * 2 + 1] = h1;
        lo[i * 2 + 0] = l0; lo[i * 2 + 1] = l1;
    }
}

// ---------------------------------------------------------------------------
// Transpose + split W[1024][1024] -> Wt hi/lo (Wt[n][k] = W[k][n])
// ---------------------------------------------------------------------------
__global__ void wsplit_kernel(const float* __restrict__ W,
                              __nv_bfloat16* __restrict__ Th,
                              __nv_bfloat16* __restrict__ Tl)
{
    __shared__ float t[32][33];
    int bx = blockIdx.x * 32, by = blockIdx.y * 32;
    int x = threadIdx.x, y = threadIdx.y;
    #pragma unroll
    for (int d = 0; d < 32; d += 8)
        t[y + d][x] = W[(size_t)(by + y + d) * D_MODEL + bx + x];
    __syncthreads();
    #pragma unroll
    for (int d = 0; d < 32; d += 8) {
        float v = t[x][y + d];
        __nv_bfloat16 h = __float2bfloat16_rn(v);
        __nv_bfloat16 l = __float2bfloat16_rn(v - __bfloat162float(h));
        size_t o = (size_t)(bx + y + d) * D_MODEL + by + x;
        Th[o] = h; Tl[o] = l;
    }
}

// ---------------------------------------------------------------------------
// Split-bf16 GEMM via mma.sync: C[M,1024] = (Ah+Al) @ (Bh+Bl)^T + bias
// A: [M][K] bf16 hi/lo row-major; B: W^T stored [n][k] bf16 hi/lo.
// CTA tile 128x128, BK=32, 3-stage cp.async pipeline.
// 8 warps, warp tile 64x32 (mt=4 x nt=4 of m16n8).
// smem per stage: 4 matrices x 128 rows x 80B = 40960 B; 3 stages = 122880 B.
// ---------------------------------------------------------------------------
#define STAGE_B   40960
#define MAT_B     10240
#define GEMM_SMEM (3 * STAGE_B)
#define KCHUNKS   32

__global__ __launch_bounds__(256, 1)
void gemm_bf16_mma(const __nv_bfloat16* __restrict__ Ah, const __nv_bfloat16* __restrict__ Al,
                   const __nv_bfloat16* __restrict__ Bh, const __nv_bfloat16* __restrict__ Bl,
                   const float* __restrict__ bias, float* __restrict__ C)
{
    extern __shared__ char smem_raw[];
    const uint32_t sbase = smem_u32(smem_raw);

    const int tid    = threadIdx.x;
    const int wid    = tid >> 5;
    const int lane   = tid & 31;
    const int warp_m = (wid >> 2) * 64;   // 0 or 64
    const int warp_n = (wid & 3) * 32;    // 0,32,64,96
    const size_t m0  = (size_t)blockIdx.y * 128;
    const size_t n0  = (size_t)blockIdx.x * 128;

    const char* src[4] = {
        (const char*)(Ah + m0 * D_MODEL),
        (const char*)(Al + m0 * D_MODEL),
        (const char*)(Bh + n0 * D_MODEL),
        (const char*)(Bl + n0 * D_MODEL)
    };

    // fill one pipeline stage: 4 matrices, 128 rows x 64B each, 80B smem stride
    auto fill = [&](int stage, int kc) {
        #pragma unroll
        for (int i = 0; i < 8; i++) {
            int c   = tid + i * 256;        // 0..2047
            int mat = c >> 9;               // 0..3
            int cc  = c & 511;
            int row = cc >> 2, col = cc & 3;
            cp16(sbase + stage * STAGE_B + mat * MAT_B + row * 80 + col * 16,
                 src[mat] + (size_t)row * 2048 + kc * 64 + col * 16);
        }
        CP_COMMIT();
    };

    float acc[4][4][4];
    #pragma unroll
    for (int i = 0; i < 4; i++)
        #pragma unroll
        for (int j = 0; j < 4; j++)
            #pragma unroll
            for (int q = 0; q < 4; q++) acc[i][j][q] = 0.f;

    fill(0, 0);
    fill(1, 1);

    // per-lane ldmatrix offsets
    const int lr = lane & 7, g = lane >> 3;
    const uint32_t a_loff = (uint32_t)((lr + (g & 1) * 8) * 80 + (g >> 1) * 16);
    const uint32_t b_loff = (uint32_t)((lr + (g >> 1) * 8) * 80 + (g & 1) * 16);

    for (int j = 0; j < KCHUNKS; j++) {
        if (j + 2 < KCHUNKS) fill((j + 2) % 3, j + 2);
        else CP_COMMIT();
        CP_WAIT2();
        __syncthreads();

        const uint32_t st = sbase + (j % 3) * STAGE_B;
        const uint32_t aH = st +              warp_m * 80 + a_loff;
        const uint32_t aL = st + 1 * MAT_B +  warp_m * 80 + a_loff;
        const uint32_t bH = st + 2 * MAT_B +  warp_n * 80 + b_loff;
        const uint32_t bL = st + 3 * MAT_B +  warp_n * 80 + b_loff;

        #pragma unroll
        for (int ks = 0; ks < 2; ks++) {
            const uint32_t ko = ks * 32;    // 16 bf16 = 32B per k-step
            uint32_t a_r[4][4], bh_r[8], bl_r[8];

            // ---- pass 1: hi*hi ----
            #pragma unroll
            for (int mt = 0; mt < 4; mt++)
                LDSM4(a_r[mt][0], a_r[mt][1], a_r[mt][2], a_r[mt][3],
                      aH + mt * (16 * 80) + ko);
            #pragma unroll
            for (int p = 0; p < 2; p++)
                LDSM4(bh_r[p*4+0], bh_r[p*4+1], bh_r[p*4+2], bh_r[p*4+3],
                      bH + p * (16 * 80) + ko);
            #pragma unroll
            for (int mt = 0; mt < 4; mt++)
                #pragma unroll
                for (int nt = 0; nt < 4; nt++)
                    MMA16816(acc[mt][nt], a_r[mt], bh_r[nt*2], bh_r[nt*2+1]);

            // ---- pass 2: hi*lo ----
            #pragma unroll
            for (int p = 0; p < 2; p++)
                LDSM4(bl_r[p*4+0], bl_r[p*4+1], bl_r[p*4+2], bl_r[p*4+3],
                      bL + p * (16 * 80) + ko);
            #pragma unroll
            for (int mt = 0; mt < 4; mt++)
                #pragma unroll
                for (int nt = 0; nt < 4; nt++)
                    MMA16816(acc[mt][nt], a_r[mt], bl_r[nt*2], bl_r[nt*2+1]);

            // ---- pass 3: lo*hi ----
            #pragma unroll
            for (int mt = 0; mt < 4; mt++)
                LDSM4(a_r[mt][0], a_r[mt][1], a_r[mt][2], a_r[mt][3],
                      aL + mt * (16 * 80) + ko);
            #pragma unroll
            for (int mt = 0; mt < 4; mt++)
                #pragma unroll
                for (int nt = 0; nt < 4; nt++)
                    MMA16816(acc[mt][nt], a_r[mt], bh_r[nt*2], bh_r[nt*2+1]);
        }
        __syncthreads();
    }

    // epilogue: acc + bias -> C (fp32)
    #pragma unroll
    for (int mt = 0; mt < 4; mt++) {
        #pragma unroll
        for (int nt = 0; nt < 4; nt++) {
            int row0 = (int)m0 + warp_m + mt * 16 + (lane >> 2);
            int colg = (int)n0 + warp_n + nt * 8 + (lane & 3) * 2;
            float2 bv = *reinterpret_cast<const float2*>(bias + colg);
            float2 o0, o1;
            o0.x = acc[mt][nt][0] + bv.x; o0.y = acc[mt][nt][1] + bv.y;
            o1.x = acc[mt][nt][2] + bv.x; o1.y = acc[mt][nt][3] + bv.y;
            *reinterpret_cast<float2*>(C + (size_t)row0 * D_MODEL + colg) = o0;
            *reinterpret_cast<float2*>(C + (size_t)(row0 + 8) * D_MODEL + colg) = o1;
        }
    }
}

// ---------------------------------------------------------------------------
// Fused patch attention (fp32), outputs bf16 hi/lo for the O-projection.
// grid = (NUM_HEADS, NBLK), 256 threads. smem 131584 B.
// ---------------------------------------------------------------------------
__global__ __launch_bounds__(256, 1)
void attn_kernel()
{
    extern __shared__ float sm[];
    float* Ks = sm;
    float* Vs = Ks + 128 * 64;
    float* S  = Vs + 128 * 64;       // [128][129]

    const int h   = blockIdx.x;
    const int pb  = blockIdx.y;
    const int tid = threadIdx.x;
    const size_t base = (size_t)pb * 128 * D_MODEL + (size_t)h * D_HEAD;

    for (int i = tid; i < 128 * 16; i += 256) {
        int row = i >> 4;
        int c   = i & 15;
        size_t gidx = base + (size_t)row * D_MODEL + c * 4;
        *reinterpret_cast<float4*>(&Ks[row * 64 + c * 4]) =
            *reinterpret_cast<const float4*>(&g_K[gidx]);
        *reinterpret_cast<float4*>(&Vs[row * 64 + c * 4]) =
            *reinterpret_cast<const float4*>(&g_V[gidx]);
    }
    __syncthreads();

    const int r    = tid >> 1;
    const int half = tid & 1;

    float q[64];
    {
        const float* qp = &g_Q[base + (size_t)r * D_MODEL];
        #pragma unroll
        for (int c = 0; c < 16; c++) {
            float4 v = *reinterpret_cast<const float4*>(qp + c * 4);
            q[c * 4 + 0] = v.x * 0.125f;
            q[c * 4 + 1] = v.y * 0.125f;
            q[c * 4 + 2] = v.z * 0.125f;
            q[c * 4 + 3] = v.w * 0.125f;
        }
    }

    #pragma unroll 1
    for (int j0 = 0; j0 < 64; j0++) {
        int j = half * 64 + j0;
        const float* kp = &Ks[j * 64];
        float s0 = 0.f, s1 = 0.f, s2 = 0.f, s3 = 0.f;
        #pragma unroll
        for (int c = 0; c < 16; c++) {
            float4 kv = *reinterpret_cast<const float4*>(kp + c * 4);
            s0 += q[c * 4 + 0] * kv.x;
            s1 += q[c * 4 + 1] * kv.y;
            s2 += q[c * 4 + 2] * kv.z;
            s3 += q[c * 4 + 3] * kv.w;
        }
        S[r * 129 + j] = (s0 + s1) + (s2 + s3);
    }
    __syncthreads();

    float mx = -CUDART_INF_F;
    #pragma unroll 4
    for (int j0 = 0; j0 < 64; j0++)
        mx = fmaxf(mx, S[r * 129 + half * 64 + j0]);
    mx = fmaxf(mx, __shfl_xor_sync(0xffffffffu, mx, 1));

    float l = 0.f;
    #pragma unroll 4
    for (int j0 = 0; j0 < 64; j0++) {
        float e = __expf(S[r * 129 + half * 64 + j0] - mx);
        S[r * 129 + half * 64 + j0] = e;
        l += e;
    }
    l += __shfl_xor_sync(0xffffffffu, l, 1);
    float inv = 1.0f / l;
    __syncthreads();

    float acc[32];
    #pragma unroll
    for (int c = 0; c < 32; c++) acc[c] = 0.f;

    #pragma unroll 1
    for (int j = 0; j < 128; j++) {
        float w = S[r * 129 + j];
        const float* vp = &Vs[j * 64 + half * 32];
        #pragma unroll
        for (int c = 0; c < 8; c++) {
            float4 vv = *reinterpret_cast<const float4*>(vp + c * 4);
            acc[c * 4 + 0] += w * vv.x;
            acc[c * 4 + 1] += w * vv.y;
            acc[c * 4 + 2] += w * vv.z;
            acc[c * 4 + 3] += w * vv.w;
        }
    }

    size_t obase = base + (size_t)r * D_MODEL + half * 32;
    __nv_bfloat162* oh = reinterpret_cast<__nv_bfloat162*>(&g_Ah[obase]);
    __nv_bfloat162* ol = reinterpret_cast<__nv_bfloat162*>(&g_Al[obase]);
    #pragma unroll
    for (int c = 0; c < 16; c++) {
        float o0 = acc[c * 2 + 0] * inv;
        float o1 = acc[c * 2 + 1] * inv;
        __nv_bfloat16 h0 = __float2bfloat16_rn(o0);
        __nv_bfloat16 h1 = __float2bfloat16_rn(o1);
        __nv_bfloat162 hp; hp.x = h0; hp.y = h1;
        __nv_bfloat162 lp;
        lp.x = __float2bfloat16_rn(o0 - __bfloat162float(h0));
        lp.y = __float2bfloat16_rn(o1 - __bfloat162float(h1));
        oh[c] = hp;
        ol[c] = lp;
    }
}

// ---------------------------------------------------------------------------
extern "C" void kernel_launch(void* const* d_in, const int* in_sizes, int n_in,
                              void* d_out, int out_size)
{
    const float* x  = (const float*)d_in[0];
    // d_in[1] = coords (unused by reference)
    const float* Wq = (const float*)d_in[2];
    const float* bq = (const float*)d_in[3];
    const float* Wk = (const float*)d_in[4];
    const float* bk = (const float*)d_in[5];
    const float* Wv = (const float*)d_in[6];
    const float* bv = (const float*)d_in[7];
    const float* Wo = (const float*)d_in[8];
    const float* bo = (const float*)d_in[9];
    float* out = (float*)d_out;

    __nv_bfloat16 *xh, *xl, *Ah, *Al;
    __nv_bfloat16 *wqh, *wql, *wkh, *wkl, *wvh, *wvl, *woh, *wol;
    float *pQ, *pK, *pV;
    cudaGetSymbolAddress((void**)&xh,  g_xh);
    cudaGetSymbolAddress((void**)&xl,  g_xl);
    cudaGetSymbolAddress((void**)&Ah,  g_Ah);
    cudaGetSymbolAddress((void**)&Al,  g_Al);
    cudaGetSymbolAddress((void**)&pQ,  g_Q);
    cudaGetSymbolAddress((void**)&pK,  g_K);
    cudaGetSymbolAddress((void**)&pV,  g_V);
    cudaGetSymbolAddress((void**)&wqh, g_wqh);
    cudaGetSymbolAddress((void**)&wql, g_wql);
    cudaGetSymbolAddress((void**)&wkh, g_wkh);
    cudaGetSymbolAddress((void**)&wkl, g_wkl);
    cudaGetSymbolAddress((void**)&wvh, g_wvh);
    cudaGetSymbolAddress((void**)&wvl, g_wvl);
    cudaGetSymbolAddress((void**)&woh, g_woh);
    cudaGetSymbolAddress((void**)&wol, g_wol);

    cudaFuncSetAttribute(gemm_bf16_mma, cudaFuncAttributeMaxDynamicSharedMemorySize, GEMM_SMEM);
    static const size_t attn_smem = (128 * 64 * 2 + 128 * 129) * sizeof(float);
    cudaFuncSetAttribute(attn_kernel, cudaFuncAttributeMaxDynamicSharedMemorySize, (int)attn_smem);

    // 1. split x -> bf16 hi/lo
    fsplit_kernel<<<8192, 256>>>((const float4*)x, (__nv_bfloat162*)xh, (__nv_bfloat162*)xl,
                                 M_TOTAL * D_MODEL / 4);
    // 2. transpose + split weights
    dim3 wgrid(32, 32), wblk(32, 8);
    wsplit_kernel<<<wgrid, wblk>>>(Wq, wqh, wql);
    wsplit_kernel<<<wgrid, wblk>>>(Wk, wkh, wkl);
    wsplit_kernel<<<wgrid, wblk>>>(Wv, wvh, wvl);
    wsplit_kernel<<<wgrid, wblk>>>(Wo, woh, wol);

    // 3. Q/K/V projections (tensor cores)
    dim3 ggrid(D_MODEL / 128, M_TOTAL / 128);   // (8, 256)
    gemm_bf16_mma<<<ggrid, 256, GEMM_SMEM>>>(xh, xl, wqh, wql, bq, pQ);
    gemm_bf16_mma<<<ggrid, 256, GEMM_SMEM>>>(xh, xl, wkh, wkl, bk, pK);
    gemm_bf16_mma<<<ggrid, 256, GEMM_SMEM>>>(xh, xl, wvh, wvl, bv, pV);

    // 4. attention (writes bf16 hi/lo)
    dim3 agrid(NUM_HEADS, NBLK);
    attn_kernel<<<agrid, 256, attn_smem>>>();

    // 5. output projection
    gemm_bf16_mma<<<ggrid, 256, GEMM_SMEM>>>(Ah, Al, woh, wol, bo, out);
}